// round 1
// baseline (speedup 1.0000x reference)
#include <cuda_runtime.h>
#include <math.h>

#define NN 10000
#define EE 320000
#define GG 64
#define HH 32

// ---- scratch (device globals; no allocation allowed) ----
__device__ float g_P[NN * HH];
__device__ float g_Q[NN * HH];
__device__ float g_bufA[NN * HH];
__device__ float g_bufB[NN * HH];
__device__ float g_add[GG * HH];
__device__ int   g_max[GG * HH];
__device__ float g_cnt[GG];

// Fused projection: P = relu?(in) @ nn_w, Q = relu?(in) @ nn_b,
// agg = relu?(in) @ root + bias   (agg seeds the scatter accumulator)
__global__ void proj_kernel(const float* __restrict__ in, int in_dim, int apply_relu,
                            const float* __restrict__ nnw, const float* __restrict__ nnb,
                            const float* __restrict__ root, const float* __restrict__ bias,
                            float* __restrict__ P, float* __restrict__ Q,
                            float* __restrict__ agg)
{
    extern __shared__ float sm[];
    float* s_w = sm;
    float* s_b = sm + in_dim * HH;
    float* s_r = sm + 2 * in_dim * HH;
    float* s_bias = sm + 3 * in_dim * HH;

    int tot = in_dim * HH;
    for (int i = threadIdx.x; i < tot; i += blockDim.x) {
        s_w[i] = nnw[i];
        s_b[i] = nnb[i];
        s_r[i] = root[i];
    }
    if (threadIdx.x < HH) s_bias[threadIdx.x] = bias[threadIdx.x];
    __syncthreads();

    int row  = blockIdx.x * 8 + (threadIdx.x >> 5);
    int lane = threadIdx.x & 31;
    if (row >= NN) return;

    const float* xr = in + (size_t)row * in_dim;
    float ap = 0.f, aq = 0.f, ar = s_bias[lane];
    #pragma unroll 4
    for (int k = 0; k < in_dim; k++) {
        float xv = xr[k];                 // warp-broadcast load
        if (apply_relu) xv = fmaxf(xv, 0.f);
        ap = fmaf(xv, s_w[k * HH + lane], ap);
        aq = fmaf(xv, s_b[k * HH + lane], aq);
        ar = fmaf(xv, s_r[k * HH + lane], ar);
    }
    int o = row * HH + lane;
    P[o] = ap;
    Q[o] = aq;
    agg[o] = ar;
}

// Edge scatter: agg[dst] += a * P[src] + Q[src], one warp per edge.
__global__ void scatter_kernel(const int* __restrict__ ei, const float* __restrict__ ea,
                               const float* __restrict__ P, const float* __restrict__ Q,
                               float* __restrict__ agg)
{
    int e = blockIdx.x * (blockDim.x >> 5) + (threadIdx.x >> 5);
    int lane = threadIdx.x & 31;
    if (e >= EE) return;
    int src = ei[e];
    int dst = ei[EE + e];
    float a = ea[e];
    float v = fmaf(a, __ldg(&P[src * HH + lane]), __ldg(&Q[src * HH + lane]));
    atomicAdd(&agg[dst * HH + lane], v);   // unused return -> RED
}

__global__ void pool_init_kernel()
{
    int i = blockIdx.x * blockDim.x + threadIdx.x;
    if (i < GG * HH) { g_add[i] = 0.f; g_max[i] = 0; }
    if (i < GG) g_cnt[i] = 0.f;
}

// Pooling: add / count / max per graph, reading relu(agg3).
__global__ void pool_kernel(const float* __restrict__ hfinal, const int* __restrict__ batch)
{
    int node = blockIdx.x * 8 + (threadIdx.x >> 5);
    int lane = threadIdx.x & 31;
    if (node >= NN) return;
    float v = fmaxf(hfinal[node * HH + lane], 0.f);  // relu of layer-3 output
    int b = batch[node];
    atomicAdd(&g_add[b * HH + lane], v);
    atomicMax(&g_max[b * HH + lane], __float_as_int(v));  // v >= 0 so int-order == float-order
    if (lane == 0) atomicAdd(&g_cnt[b], 1.0f);
}

// Readout: g=[add,mean,max] (96) -> relu(lin1) (32) -> lin2 (2) -> log_softmax
__global__ void readout_kernel(const float* __restrict__ lin1_w, const float* __restrict__ lin1_b,
                               const float* __restrict__ lin2_w, const float* __restrict__ lin2_b,
                               float* __restrict__ out)
{
    __shared__ float g[3 * HH];
    __shared__ float h1[HH];
    int gi = blockIdx.x;
    int t = threadIdx.x;

    float add = g_add[gi * HH + t];
    float cnt = fmaxf(g_cnt[gi], 1.0f);
    g[t]          = add;
    g[HH + t]     = add / cnt;
    g[2 * HH + t] = __int_as_float(g_max[gi * HH + t]);
    __syncthreads();

    float acc = lin1_b[t];
    #pragma unroll
    for (int k = 0; k < 3 * HH; k++)
        acc = fmaf(g[k], lin1_w[k * HH + t], acc);
    h1[t] = fmaxf(acc, 0.f);
    __syncthreads();

    if (t == 0) {
        float l0 = lin2_b[0], l1 = lin2_b[1];
        #pragma unroll
        for (int k = 0; k < HH; k++) {
            l0 = fmaf(h1[k], lin2_w[k * 2 + 0], l0);
            l1 = fmaf(h1[k], lin2_w[k * 2 + 1], l1);
        }
        float m = fmaxf(l0, l1);
        float lse = m + logf(expf(l0 - m) + expf(l1 - m));
        out[gi * 2 + 0] = l0 - lse;
        out[gi * 2 + 1] = l1 - lse;
    }
}

extern "C" void kernel_launch(void* const* d_in, const int* in_sizes, int n_in,
                              void* d_out, int out_size)
{
    const float* x      = (const float*)d_in[0];
    const int*   ei     = (const int*)d_in[1];
    const float* ea     = (const float*)d_in[2];
    const int*   batch  = (const int*)d_in[3];
    const float* nn_w1  = (const float*)d_in[4];
    const float* nn_b1  = (const float*)d_in[5];
    const float* root1  = (const float*)d_in[6];
    const float* bias1  = (const float*)d_in[7];
    const float* nn_w2  = (const float*)d_in[8];
    const float* nn_b2  = (const float*)d_in[9];
    const float* root2  = (const float*)d_in[10];
    const float* bias2  = (const float*)d_in[11];
    const float* nn_w3  = (const float*)d_in[12];
    const float* nn_b3  = (const float*)d_in[13];
    const float* root3  = (const float*)d_in[14];
    const float* bias3  = (const float*)d_in[15];
    const float* lin1_w = (const float*)d_in[16];
    const float* lin1_b = (const float*)d_in[17];
    const float* lin2_w = (const float*)d_in[18];
    const float* lin2_b = (const float*)d_in[19];
    float* out = (float*)d_out;

    float *dP, *dQ, *dA, *dB;
    cudaGetSymbolAddress((void**)&dP, g_P);
    cudaGetSymbolAddress((void**)&dQ, g_Q);
    cudaGetSymbolAddress((void**)&dA, g_bufA);
    cudaGetSymbolAddress((void**)&dB, g_bufB);

    const int projGrid = (NN + 7) / 8;          // 1250 blocks, 8 rows each
    const int scatGrid = (EE + 7) / 8;          // 40000 blocks, 8 edges each
    const size_t smem33 = (3 * 33 * HH + HH) * sizeof(float);
    const size_t smem32 = (3 * 32 * HH + HH) * sizeof(float);

    // layer 1: in = x [N,33]
    proj_kernel<<<projGrid, 256, smem33>>>(x, 33, 0, nn_w1, nn_b1, root1, bias1, dP, dQ, dA);
    scatter_kernel<<<scatGrid, 256>>>(ei, ea, dP, dQ, dA);
    // layer 2: in = relu(aggA)
    proj_kernel<<<projGrid, 256, smem32>>>(dA, 32, 1, nn_w2, nn_b2, root2, bias2, dP, dQ, dB);
    scatter_kernel<<<scatGrid, 256>>>(ei, ea, dP, dQ, dB);
    // layer 3: in = relu(aggB)
    proj_kernel<<<projGrid, 256, smem32>>>(dB, 32, 1, nn_w3, nn_b3, root3, bias3, dP, dQ, dA);
    scatter_kernel<<<scatGrid, 256>>>(ei, ea, dP, dQ, dA);

    // pooling + readout
    pool_init_kernel<<<(GG * HH + 255) / 256, 256>>>();
    pool_kernel<<<projGrid, 256>>>(dA, batch);
    readout_kernel<<<GG, HH>>>(lin1_w, lin1_b, lin2_w, lin2_b, out);
}

// round 2
// speedup vs baseline: 1.1297x; 1.1297x over previous
#include <cuda_runtime.h>
#include <math.h>

#define NN 10000
#define EE 320000
#define GG 64
#define HH 32

// ---- scratch (device globals; no allocation allowed) ----
__device__ float2 g_PQ[NN * HH];        // interleaved {P, Q} per (node, lane)
__device__ float  g_bufA[NN * HH];
__device__ float  g_bufB[NN * HH];
__device__ int    g_count[NN];
__device__ int    g_off[NN + 1];
__device__ int    g_cur[NN];
__device__ float2 g_ep[EE];             // packed {src_as_float_bits, attr}, sorted by dst
__device__ float  g_add[GG * HH];
__device__ int    g_max[GG * HH];
__device__ float  g_cnt[GG];

// ---------------- CSR build ----------------
__global__ void zero_kernel()
{
    int i = blockIdx.x * blockDim.x + threadIdx.x;
    if (i < NN) g_count[i] = 0;
    if (i < GG * HH) { g_add[i] = 0.f; g_max[i] = 0; }
    if (i < GG) g_cnt[i] = 0.f;
}

__global__ void hist_kernel(const int* __restrict__ ei)
{
    int e = blockIdx.x * blockDim.x + threadIdx.x;
    if (e >= EE) return;
    atomicAdd(&g_count[ei[EE + e]], 1);
}

// single-block exclusive scan over 10000 counts (1024 threads, 10 elems each)
__global__ void scan_kernel()
{
    __shared__ int s[1024];
    int t = threadIdx.x;
    const int CH = 10;
    int base = t * CH;
    int loc[CH];
    int sum = 0;
    #pragma unroll
    for (int i = 0; i < CH; i++) {
        int idx = base + i;
        int v = (idx < NN) ? g_count[idx] : 0;
        loc[i] = sum;
        sum += v;
    }
    s[t] = sum;
    __syncthreads();
    // Kogge-Stone inclusive scan
    for (int off = 1; off < 1024; off <<= 1) {
        int v = (t >= off) ? s[t - off] : 0;
        __syncthreads();
        s[t] += v;
        __syncthreads();
    }
    int excl = (t > 0) ? s[t - 1] : 0;
    #pragma unroll
    for (int i = 0; i < CH; i++) {
        int idx = base + i;
        if (idx < NN) {
            int o = excl + loc[i];
            g_off[idx] = o;
            g_cur[idx] = o;
        }
    }
    if (t == 1023) g_off[NN] = s[1023];
}

__global__ void permute_kernel(const int* __restrict__ ei, const float* __restrict__ ea)
{
    int e = blockIdx.x * blockDim.x + threadIdx.x;
    if (e >= EE) return;
    int src = ei[e];
    int dst = ei[EE + e];
    float a = ea[e];
    int pos = atomicAdd(&g_cur[dst], 1);
    g_ep[pos] = make_float2(__int_as_float(src), a);
}

// ---------------- per-layer kernels ----------------
// Fused projection: PQ = {relu?(in) @ nn_w, relu?(in) @ nn_b},
// agg = relu?(in) @ root + bias   (agg seeds the gather accumulator)
__global__ void proj_kernel(const float* __restrict__ in, int in_dim, int apply_relu,
                            const float* __restrict__ nnw, const float* __restrict__ nnb,
                            const float* __restrict__ root, const float* __restrict__ bias,
                            float2* __restrict__ PQ, float* __restrict__ agg)
{
    extern __shared__ float sm[];
    float* s_w = sm;
    float* s_b = sm + in_dim * HH;
    float* s_r = sm + 2 * in_dim * HH;
    float* s_bias = sm + 3 * in_dim * HH;

    int tot = in_dim * HH;
    for (int i = threadIdx.x; i < tot; i += blockDim.x) {
        s_w[i] = nnw[i];
        s_b[i] = nnb[i];
        s_r[i] = root[i];
    }
    if (threadIdx.x < HH) s_bias[threadIdx.x] = bias[threadIdx.x];
    __syncthreads();

    int row  = blockIdx.x * 8 + (threadIdx.x >> 5);
    int lane = threadIdx.x & 31;
    if (row >= NN) return;

    const float* xr = in + (size_t)row * in_dim;
    float ap = 0.f, aq = 0.f, ar = s_bias[lane];
    #pragma unroll 4
    for (int k = 0; k < in_dim; k++) {
        float xv = xr[k];
        if (apply_relu) xv = fmaxf(xv, 0.f);
        ap = fmaf(xv, s_w[k * HH + lane], ap);
        aq = fmaf(xv, s_b[k * HH + lane], aq);
        ar = fmaf(xv, s_r[k * HH + lane], ar);
    }
    int o = row * HH + lane;
    PQ[o] = make_float2(ap, aq);
    agg[o] = ar;
}

// Gather-sum over CSR bucket: agg[i] += sum_j a_j * P[s_j] + Q[s_j]. No atomics.
__global__ void gather_kernel(const float2* __restrict__ PQ, float* __restrict__ agg)
{
    int node = blockIdx.x * 8 + (threadIdx.x >> 5);
    int lane = threadIdx.x & 31;
    if (node >= NN) return;

    int beg = g_off[node];
    int end = g_off[node + 1];
    int o = node * HH + lane;
    float v0 = agg[o];
    float v1 = 0.f;

    int j = beg;
    for (; j + 1 < end; j += 2) {
        float2 e0 = __ldg(&g_ep[j]);
        float2 e1 = __ldg(&g_ep[j + 1]);
        int s0 = __float_as_int(e0.x);
        int s1 = __float_as_int(e1.x);
        float2 pq0 = __ldg(&PQ[s0 * HH + lane]);
        float2 pq1 = __ldg(&PQ[s1 * HH + lane]);
        v0 += fmaf(e0.y, pq0.x, pq0.y);
        v1 += fmaf(e1.y, pq1.x, pq1.y);
    }
    if (j < end) {
        float2 e0 = __ldg(&g_ep[j]);
        int s0 = __float_as_int(e0.x);
        float2 pq0 = __ldg(&PQ[s0 * HH + lane]);
        v0 += fmaf(e0.y, pq0.x, pq0.y);
    }
    agg[o] = v0 + v1;
}

// ---------------- pooling + readout ----------------
__global__ void pool_kernel(const float* __restrict__ hfinal, const int* __restrict__ batch)
{
    int node = blockIdx.x * 8 + (threadIdx.x >> 5);
    int lane = threadIdx.x & 31;
    if (node >= NN) return;
    float v = fmaxf(hfinal[node * HH + lane], 0.f);   // relu of layer-3 output
    int b = batch[node];
    atomicAdd(&g_add[b * HH + lane], v);
    atomicMax(&g_max[b * HH + lane], __float_as_int(v)); // v >= 0: int order == float order
    if (lane == 0) atomicAdd(&g_cnt[b], 1.0f);
}

__global__ void readout_kernel(const float* __restrict__ lin1_w, const float* __restrict__ lin1_b,
                               const float* __restrict__ lin2_w, const float* __restrict__ lin2_b,
                               float* __restrict__ out)
{
    __shared__ float g[3 * HH];
    __shared__ float h1[HH];
    int gi = blockIdx.x;
    int t = threadIdx.x;

    float add = g_add[gi * HH + t];
    float cnt = fmaxf(g_cnt[gi], 1.0f);
    g[t]          = add;
    g[HH + t]     = add / cnt;
    g[2 * HH + t] = __int_as_float(g_max[gi * HH + t]);
    __syncthreads();

    float acc = lin1_b[t];
    #pragma unroll
    for (int k = 0; k < 3 * HH; k++)
        acc = fmaf(g[k], lin1_w[k * HH + t], acc);
    h1[t] = fmaxf(acc, 0.f);
    __syncthreads();

    if (t == 0) {
        float l0 = lin2_b[0], l1 = lin2_b[1];
        #pragma unroll
        for (int k = 0; k < HH; k++) {
            l0 = fmaf(h1[k], lin2_w[k * 2 + 0], l0);
            l1 = fmaf(h1[k], lin2_w[k * 2 + 1], l1);
        }
        float m = fmaxf(l0, l1);
        float lse = m + logf(expf(l0 - m) + expf(l1 - m));
        out[gi * 2 + 0] = l0 - lse;
        out[gi * 2 + 1] = l1 - lse;
    }
}

extern "C" void kernel_launch(void* const* d_in, const int* in_sizes, int n_in,
                              void* d_out, int out_size)
{
    const float* x      = (const float*)d_in[0];
    const int*   ei     = (const int*)d_in[1];
    const float* ea     = (const float*)d_in[2];
    const int*   batch  = (const int*)d_in[3];
    const float* nn_w1  = (const float*)d_in[4];
    const float* nn_b1  = (const float*)d_in[5];
    const float* root1  = (const float*)d_in[6];
    const float* bias1  = (const float*)d_in[7];
    const float* nn_w2  = (const float*)d_in[8];
    const float* nn_b2  = (const float*)d_in[9];
    const float* root2  = (const float*)d_in[10];
    const float* bias2  = (const float*)d_in[11];
    const float* nn_w3  = (const float*)d_in[12];
    const float* nn_b3  = (const float*)d_in[13];
    const float* root3  = (const float*)d_in[14];
    const float* bias3  = (const float*)d_in[15];
    const float* lin1_w = (const float*)d_in[16];
    const float* lin1_b = (const float*)d_in[17];
    const float* lin2_w = (const float*)d_in[18];
    const float* lin2_b = (const float*)d_in[19];
    float* out = (float*)d_out;

    float2 *dPQ;
    float *dA, *dB;
    cudaGetSymbolAddress((void**)&dPQ, g_PQ);
    cudaGetSymbolAddress((void**)&dA, g_bufA);
    cudaGetSymbolAddress((void**)&dB, g_bufB);

    const int nodeGrid = (NN + 7) / 8;           // warp per node
    const int edgeGrid = (EE + 255) / 256;
    const size_t smem33 = (3 * 33 * HH + HH) * sizeof(float);
    const size_t smem32 = (3 * 32 * HH + HH) * sizeof(float);

    // CSR build (per launch) + pooling-accumulator init
    zero_kernel<<<(NN + 255) / 256, 256>>>();
    hist_kernel<<<edgeGrid, 256>>>(ei);
    scan_kernel<<<1, 1024>>>();
    permute_kernel<<<edgeGrid, 256>>>(ei, ea);

    // layer 1: in = x [N,33]
    proj_kernel<<<nodeGrid, 256, smem33>>>(x, 33, 0, nn_w1, nn_b1, root1, bias1, dPQ, dA);
    gather_kernel<<<nodeGrid, 256>>>(dPQ, dA);
    // layer 2: in = relu(A)
    proj_kernel<<<nodeGrid, 256, smem32>>>(dA, 32, 1, nn_w2, nn_b2, root2, bias2, dPQ, dB);
    gather_kernel<<<nodeGrid, 256>>>(dPQ, dB);
    // layer 3: in = relu(B)
    proj_kernel<<<nodeGrid, 256, smem32>>>(dB, 32, 1, nn_w3, nn_b3, root3, bias3, dPQ, dA);
    gather_kernel<<<nodeGrid, 256>>>(dPQ, dA);

    // pooling + readout
    pool_kernel<<<nodeGrid, 256>>>(dA, batch);
    readout_kernel<<<GG, HH>>>(lin1_w, lin1_b, lin2_w, lin2_b, out);
}

// round 3
// speedup vs baseline: 1.2029x; 1.0648x over previous
#include <cuda_runtime.h>
#include <math.h>

#define NN 10000
#define EE 320000
#define GG 64
#define HH 32

// ---- scratch (device globals; no allocation allowed) ----
__device__ float2 g_PQ1[NN * HH];
__device__ float2 g_PQ2[NN * HH];
__device__ float  g_bufA[NN * HH];
__device__ float  g_bufB[NN * HH];
__device__ int    g_count[NN];
__device__ int    g_off[NN + 1];
__device__ int    g_cur[NN];
__device__ float2 g_ep[EE];             // packed {src bits, attr}, sorted by dst
__device__ float  g_add[GG * HH];
__device__ int    g_max[GG * HH];
__device__ float  g_cnt[GG];

// ---------------- CSR build ----------------
__global__ void hist_kernel(const int* __restrict__ ei)
{
    int e = (blockIdx.x * blockDim.x + threadIdx.x) * 4;
    if (e >= EE) return;
    int4 d = *(const int4*)(ei + EE + e);
    atomicAdd(&g_count[d.x], 1);
    atomicAdd(&g_count[d.y], 1);
    atomicAdd(&g_count[d.z], 1);
    atomicAdd(&g_count[d.w], 1);
}

// single-block exclusive scan over 10000 counts; also zeroes pooling accumulators
__global__ void scan_kernel()
{
    __shared__ int s[1024];
    int t = threadIdx.x;

    // zero pooling accumulators (free: idle bandwidth in this tiny kernel)
    if (t < GG * HH) { g_add[t] = 0.f; g_add[t + 1024] = 0.f * 0.f; }
    if (t < GG * HH) { }
    for (int i = t; i < GG * HH; i += 1024) { g_add[i] = 0.f; g_max[i] = 0; }
    if (t < GG) g_cnt[t] = 0.f;

    const int CH = 10;
    int base = t * CH;
    int loc[CH];
    int sum = 0;
    #pragma unroll
    for (int i = 0; i < CH; i++) {
        int idx = base + i;
        int v = (idx < NN) ? g_count[idx] : 0;
        loc[i] = sum;
        sum += v;
    }
    s[t] = sum;
    __syncthreads();
    for (int off = 1; off < 1024; off <<= 1) {
        int v = (t >= off) ? s[t - off] : 0;
        __syncthreads();
        s[t] += v;
        __syncthreads();
    }
    int excl = (t > 0) ? s[t - 1] : 0;
    #pragma unroll
    for (int i = 0; i < CH; i++) {
        int idx = base + i;
        if (idx < NN) {
            int o = excl + loc[i];
            g_off[idx] = o;
            g_cur[idx] = o;
        }
    }
    if (t == 1023) g_off[NN] = s[1023];
}

__global__ void permute_kernel(const int* __restrict__ ei, const float* __restrict__ ea)
{
    int e = (blockIdx.x * blockDim.x + threadIdx.x) * 4;
    if (e >= EE) return;
    int4 sidx = *(const int4*)(ei + e);
    int4 didx = *(const int4*)(ei + EE + e);
    float4 a  = *(const float4*)(ea + e);
    int p0 = atomicAdd(&g_cur[didx.x], 1);
    int p1 = atomicAdd(&g_cur[didx.y], 1);
    int p2 = atomicAdd(&g_cur[didx.z], 1);
    int p3 = atomicAdd(&g_cur[didx.w], 1);
    g_ep[p0] = make_float2(__int_as_float(sidx.x), a.x);
    g_ep[p1] = make_float2(__int_as_float(sidx.y), a.y);
    g_ep[p2] = make_float2(__int_as_float(sidx.z), a.z);
    g_ep[p3] = make_float2(__int_as_float(sidx.w), a.w);
}

// ---------------- layer 1 projection (in_dim = 33) ----------------
__global__ void proj1_kernel(const float* __restrict__ in,
                             const float* __restrict__ nnw, const float* __restrict__ nnb,
                             const float* __restrict__ root, const float* __restrict__ bias,
                             float2* __restrict__ PQ, float* __restrict__ seed)
{
    const int IND = 33;
    __shared__ float s_w[IND * HH], s_b[IND * HH], s_r[IND * HH], s_bias[HH];
    for (int i = threadIdx.x; i < IND * HH; i += blockDim.x) {
        s_w[i] = nnw[i];
        s_b[i] = nnb[i];
        s_r[i] = root[i];
    }
    if (threadIdx.x < HH) s_bias[threadIdx.x] = bias[threadIdx.x];
    __syncthreads();

    int row  = blockIdx.x * 8 + (threadIdx.x >> 5);
    int lane = threadIdx.x & 31;
    if (row >= NN) return;

    const float* xr = in + (size_t)row * IND;
    float ap = 0.f, aq = 0.f, ar = s_bias[lane];
    #pragma unroll
    for (int k = 0; k < IND; k++) {
        float xv = xr[k];
        ap = fmaf(xv, s_w[k * HH + lane], ap);
        aq = fmaf(xv, s_b[k * HH + lane], aq);
        ar = fmaf(xv, s_r[k * HH + lane], ar);
    }
    int o = row * HH + lane;
    PQ[o] = make_float2(ap, aq);
    seed[o] = ar;
}

// gather core: returns this (node, lane)'s final pre-relu hidden value
__device__ __forceinline__ float gather_row(const float2* __restrict__ PQ,
                                            const float* __restrict__ seedIn,
                                            int node, int lane)
{
    int beg = g_off[node];
    int end = g_off[node + 1];
    float v0 = seedIn[node * HH + lane];
    float v1 = 0.f, v2 = 0.f, v3 = 0.f;

    int j = beg;
    for (; j + 3 < end; j += 4) {
        float2 e0 = __ldg(&g_ep[j]);
        float2 e1 = __ldg(&g_ep[j + 1]);
        float2 e2 = __ldg(&g_ep[j + 2]);
        float2 e3 = __ldg(&g_ep[j + 3]);
        float2 pq0 = __ldg(&PQ[__float_as_int(e0.x) * HH + lane]);
        float2 pq1 = __ldg(&PQ[__float_as_int(e1.x) * HH + lane]);
        float2 pq2 = __ldg(&PQ[__float_as_int(e2.x) * HH + lane]);
        float2 pq3 = __ldg(&PQ[__float_as_int(e3.x) * HH + lane]);
        v0 += fmaf(e0.y, pq0.x, pq0.y);
        v1 += fmaf(e1.y, pq1.x, pq1.y);
        v2 += fmaf(e2.y, pq2.x, pq2.y);
        v3 += fmaf(e3.y, pq3.x, pq3.y);
    }
    for (; j < end; j++) {
        float2 e0 = __ldg(&g_ep[j]);
        float2 pq0 = __ldg(&PQ[__float_as_int(e0.x) * HH + lane]);
        v0 += fmaf(e0.y, pq0.x, pq0.y);
    }
    return (v0 + v1) + (v2 + v3);
}

// Gather layer L, then fused projection for layer L+1 (via warp shuffles).
__global__ void gather_proj_kernel(const float2* __restrict__ PQ,
                                   const float* __restrict__ seedIn,
                                   const float* __restrict__ nnw, const float* __restrict__ nnb,
                                   const float* __restrict__ root, const float* __restrict__ bias,
                                   float2* __restrict__ PQout, float* __restrict__ seedOut)
{
    __shared__ float s_w[HH * HH], s_b[HH * HH], s_r[HH * HH], s_bias[HH];
    for (int i = threadIdx.x; i < HH * HH; i += blockDim.x) {
        s_w[i] = nnw[i];
        s_b[i] = nnb[i];
        s_r[i] = root[i];
    }
    if (threadIdx.x < HH) s_bias[threadIdx.x] = bias[threadIdx.x];
    __syncthreads();

    int node = blockIdx.x * 8 + (threadIdx.x >> 5);
    int lane = threadIdx.x & 31;
    if (node >= NN) return;

    float h = fmaxf(gather_row(PQ, seedIn, node, lane), 0.f);  // relu(layer output)

    float ap = 0.f, aq = 0.f, ar = s_bias[lane];
    #pragma unroll
    for (int k = 0; k < HH; k++) {
        float xv = __shfl_sync(0xffffffffu, h, k);
        ap = fmaf(xv, s_w[k * HH + lane], ap);
        aq = fmaf(xv, s_b[k * HH + lane], aq);
        ar = fmaf(xv, s_r[k * HH + lane], ar);
    }
    int o = node * HH + lane;
    PQout[o] = make_float2(ap, aq);
    seedOut[o] = ar;
}

// Final gather (layer 3) with fused pooling.
__global__ void gather_pool_kernel(const float2* __restrict__ PQ,
                                   const float* __restrict__ seedIn,
                                   const int* __restrict__ batch)
{
    int node = blockIdx.x * 8 + (threadIdx.x >> 5);
    int lane = threadIdx.x & 31;
    if (node >= NN) return;

    float v = fmaxf(gather_row(PQ, seedIn, node, lane), 0.f);
    int b = batch[node];
    atomicAdd(&g_add[b * HH + lane], v);
    atomicMax(&g_max[b * HH + lane], __float_as_int(v)); // v >= 0: int order == float order
    if (lane == 0) atomicAdd(&g_cnt[b], 1.0f);
}

// Readout: g=[add,mean,max] (96) -> relu(lin1) (32) -> lin2 (2) -> log_softmax
__global__ void readout_kernel(const float* __restrict__ lin1_w, const float* __restrict__ lin1_b,
                               const float* __restrict__ lin2_w, const float* __restrict__ lin2_b,
                               float* __restrict__ out)
{
    __shared__ float g[3 * HH];
    __shared__ float h1[HH];
    int gi = blockIdx.x;
    int t = threadIdx.x;

    float add = g_add[gi * HH + t];
    float cnt = fmaxf(g_cnt[gi], 1.0f);
    g[t]          = add;
    g[HH + t]     = add / cnt;
    g[2 * HH + t] = __int_as_float(g_max[gi * HH + t]);
    __syncthreads();

    float acc = lin1_b[t];
    #pragma unroll
    for (int k = 0; k < 3 * HH; k++)
        acc = fmaf(g[k], lin1_w[k * HH + t], acc);
    h1[t] = fmaxf(acc, 0.f);
    __syncthreads();

    if (t == 0) {
        float l0 = lin2_b[0], l1 = lin2_b[1];
        #pragma unroll
        for (int k = 0; k < HH; k++) {
            l0 = fmaf(h1[k], lin2_w[k * 2 + 0], l0);
            l1 = fmaf(h1[k], lin2_w[k * 2 + 1], l1);
        }
        float m = fmaxf(l0, l1);
        float lse = m + logf(expf(l0 - m) + expf(l1 - m));
        out[gi * 2 + 0] = l0 - lse;
        out[gi * 2 + 1] = l1 - lse;
    }
}

extern "C" void kernel_launch(void* const* d_in, const int* in_sizes, int n_in,
                              void* d_out, int out_size)
{
    const float* x      = (const float*)d_in[0];
    const int*   ei     = (const int*)d_in[1];
    const float* ea     = (const float*)d_in[2];
    const int*   batch  = (const int*)d_in[3];
    const float* nn_w1  = (const float*)d_in[4];
    const float* nn_b1  = (const float*)d_in[5];
    const float* root1  = (const float*)d_in[6];
    const float* bias1  = (const float*)d_in[7];
    const float* nn_w2  = (const float*)d_in[8];
    const float* nn_b2  = (const float*)d_in[9];
    const float* root2  = (const float*)d_in[10];
    const float* bias2  = (const float*)d_in[11];
    const float* nn_w3  = (const float*)d_in[12];
    const float* nn_b3  = (const float*)d_in[13];
    const float* root3  = (const float*)d_in[14];
    const float* bias3  = (const float*)d_in[15];
    const float* lin1_w = (const float*)d_in[16];
    const float* lin1_b = (const float*)d_in[17];
    const float* lin2_w = (const float*)d_in[18];
    const float* lin2_b = (const float*)d_in[19];
    float* out = (float*)d_out;

    float2 *dPQ1, *dPQ2;
    float *dA, *dB;
    int *dCount;
    cudaGetSymbolAddress((void**)&dPQ1, g_PQ1);
    cudaGetSymbolAddress((void**)&dPQ2, g_PQ2);
    cudaGetSymbolAddress((void**)&dA, g_bufA);
    cudaGetSymbolAddress((void**)&dB, g_bufB);
    cudaGetSymbolAddress((void**)&dCount, g_count);

    const int nodeGrid  = (NN + 7) / 8;              // warp per node
    const int edgeGrid4 = (EE / 4 + 255) / 256;      // 4 edges per thread

    // CSR build
    cudaMemsetAsync(dCount, 0, NN * sizeof(int));
    hist_kernel<<<edgeGrid4, 256>>>(ei);
    scan_kernel<<<1, 1024>>>();
    permute_kernel<<<edgeGrid4, 256>>>(ei, ea);

    // layer 1 projection from x [N,33]
    proj1_kernel<<<nodeGrid, 256>>>(x, nn_w1, nn_b1, root1, bias1, dPQ1, dA);
    // gather L1 + proj L2
    gather_proj_kernel<<<nodeGrid, 256>>>(dPQ1, dA, nn_w2, nn_b2, root2, bias2, dPQ2, dB);
    // gather L2 + proj L3
    gather_proj_kernel<<<nodeGrid, 256>>>(dPQ2, dB, nn_w3, nn_b3, root3, bias3, dPQ1, dA);
    // gather L3 + pooling
    gather_pool_kernel<<<nodeGrid, 256>>>(dPQ1, dA, batch);

    readout_kernel<<<GG, HH>>>(lin1_w, lin1_b, lin2_w, lin2_b, out);
}